// round 1
// baseline (speedup 1.0000x reference)
#include <cuda_runtime.h>
#include <cstdint>

// Problem constants
#define B_  8
#define C_  64
#define H_  64
#define W_  64
#define NN  9          // K*K
#define M_  18         // 2*N offset channels
#define HP  66         // padded H
#define KTOT 576       // C_ * NN

// Scratch (device globals: allocation-free rule)
__device__ float g_offset[B_ * M_ * H_ * W_];   // (b, m, h, w)
__device__ float g_Wt[KTOT * C_];               // Wt[k][co] = W_conv[co][k]

// ---------------------------------------------------------------------------
// K0: transpose W_conv (co, ci, 3, 3) -> Wt[k][co], k = ci*9 + n
// ---------------------------------------------------------------------------
__global__ void k0_transpose_w(const float* __restrict__ Wc) {
    int i = blockIdx.x * 256 + threadIdx.x;
    if (i < C_ * KTOT) {
        int co = i / KTOT;
        int k  = i % KTOT;
        g_Wt[k * C_ + co] = Wc[i];
    }
}

// ---------------------------------------------------------------------------
// K1: offset conv  offset[b,m,h,w] = sum_{ci,u,v} x[b,ci,h+u-1,w+v-1]*Woff[m,ci,u,v] + b_off[m]
// Block: 16x16 pixel tile of one image. smem: x tile (64x18x18) + Woff padded.
// ---------------------------------------------------------------------------
#define K1_SMEM ((64*18*18 + 18*64*12) * 4)

__global__ __launch_bounds__(256, 1)
void k1_offset_conv(const float* __restrict__ x,
                    const float* __restrict__ Woff,
                    const float* __restrict__ boff) {
    extern __shared__ float smem[];
    float* xs = smem;                 // [ci][18][18]
    float* ws = smem + 64 * 324;      // [m][ci][12] (9 used, padded to 12 for float4 align)

    const int tid = threadIdx.x;
    const int b   = blockIdx.z;
    const int th0 = blockIdx.y * 16;
    const int tw0 = blockIdx.x * 16;

    // load x tile (zero-padded borders)
    const float* xb = x + (size_t)b * C_ * H_ * W_;
    for (int idx = tid; idx < 64 * 324; idx += 256) {
        int ci = idx / 324;
        int rem = idx % 324;
        int r = rem / 18, c = rem % 18;
        int gh = th0 + r - 1, gw = tw0 + c - 1;
        float v = 0.f;
        if ((unsigned)gh < H_ && (unsigned)gw < W_)
            v = xb[(ci * H_ + gh) * W_ + gw];
        xs[idx] = v;
    }
    // load weights into padded layout
    for (int idx = tid; idx < M_ * 64 * 9; idx += 256) {
        int m  = idx / 576;
        int rem = idx % 576;
        int ci = rem / 9, t = rem % 9;
        ws[(m * 64 + ci) * 12 + t] = Woff[idx];
    }
    __syncthreads();

    const int lh = tid >> 4, lw = tid & 15;
    float acc[M_];
#pragma unroll
    for (int m = 0; m < M_; m++) acc[m] = boff[m];

    for (int ci = 0; ci < 64; ci++) {
        float xv[9];
        const float* xc = xs + ci * 324 + lh * 18 + lw;
#pragma unroll
        for (int u = 0; u < 3; u++)
#pragma unroll
            for (int v = 0; v < 3; v++)
                xv[u * 3 + v] = xc[u * 18 + v];
#pragma unroll
        for (int m = 0; m < M_; m++) {
            const float* wp = ws + (m * 64 + ci) * 12;
            float4 wa = *(const float4*)wp;
            float4 wb = *(const float4*)(wp + 4);
            float  w8 = wp[8];
            acc[m] += xv[0]*wa.x + xv[1]*wa.y + xv[2]*wa.z + xv[3]*wa.w
                    + xv[4]*wb.x + xv[5]*wb.y + xv[6]*wb.z + xv[7]*wb.w
                    + xv[8]*w8;
        }
    }

    const int h = th0 + lh, w = tw0 + lw;
#pragma unroll
    for (int m = 0; m < M_; m++)
        g_offset[((b * M_ + m) * H_ + h) * W_ + w] = acc[m];
}

// ---------------------------------------------------------------------------
// K2: fused bilinear sampling + final GEMM.
// One block per (b, h) row of 64 output pixels.
//   Phase A: 9*64 sample coords + bilinear weights -> smem meta
//   Phase B: gather xo[k=ci*9+n][px] (576 x 64) into smem
//   Phase C: out[co][px] = sum_k Wt[k][co] * xo[k][px]  (4px x 4co per thread)
// ---------------------------------------------------------------------------
#define XO_FLOATS (KTOT * 64)            // 36864
#define WS_FLOATS (64 * 64)              // 4096
#define SQ_FLOATS (KTOT / 1 * 0 + 576 * 4)  // int4 x 576 -> 2304 "floats"
#define SG_FLOATS (576 * 4)              // float4 x 576
#define K2_SMEM ((XO_FLOATS + WS_FLOATS + SQ_FLOATS + SG_FLOATS) * 4)

__global__ __launch_bounds__(256, 1)
void k2_sample_gemm(const float* __restrict__ x, float* __restrict__ out) {
    extern __shared__ float smem[];
    float*  xo_s = smem;                             // [576][64]
    float*  w_s  = smem + XO_FLOATS;                 // [64][64]
    int4*   s_q  = (int4*)(smem + XO_FLOATS + WS_FLOATS);        // [9*64]
    float4* s_g  = (float4*)(smem + XO_FLOATS + WS_FLOATS + SQ_FLOATS); // [9*64]

    const int tid = threadIdx.x;
    const int h   = blockIdx.x;
    const int b   = blockIdx.y;

    // ---- Phase A: sample positions / weights -------------------------------
    for (int t = tid; t < NN * 64; t += 256) {
        int n  = t / 64;
        int px = t % 64;
        float offx = g_offset[((b * M_ + n)      * H_ + h) * W_ + px];
        float offy = g_offset[((b * M_ + 9 + n)  * H_ + h) * W_ + px];
        float pX = (float)(h + 1)  + (float)(n / 3 - 1) + offx;
        float pY = (float)(px + 1) + (float)(n % 3 - 1) + offy;
        float fx = floorf(pX), fy = floorf(pY);
        int x0 = min(max((int)fx,     0), HP - 1);
        int x1 = min(max((int)fx + 1, 0), HP - 1);
        int y0 = min(max((int)fy,     0), HP - 1);
        int y1 = min(max((int)fy + 1, 0), HP - 1);
        float pxc = fminf(fmaxf(pX, 0.f), (float)(HP - 1));
        float pyc = fminf(fmaxf(pY, 0.f), (float)(HP - 1));
        float gx0 = 1.f + (float)x0 - pxc;   // lt factor (x)
        float gx1 = 1.f - ((float)x1 - pxc); // rb factor (x)
        float gy0 = 1.f + (float)y0 - pyc;
        float gy1 = 1.f - ((float)y1 - pyc);
        s_q[t] = make_int4(x0, y0, x1, y1);
        s_g[t] = make_float4(gx0 * gy0, gx1 * gy1, gx0 * gy1, gx1 * gy0);
    }
    __syncthreads();

    // ---- Phase B: gather sampled matrix xo[k][px] --------------------------
    const int warp = tid >> 5;
    const int lane = tid & 31;
    const float* xbase = x + (size_t)b * C_ * H_ * W_;
    for (int t = warp; t < KTOT; t += 8) {
        int ci = t / 9;
        int n  = t % 9;
        const float* xc = xbase + ci * (H_ * W_);
#pragma unroll
        for (int half = 0; half < 2; half++) {
            int px = half * 32 + lane;
            int mi = n * 64 + px;
            int4   q = s_q[mi];
            float4 g = s_g[mi];
            int x0 = q.x - 1, y0 = q.y - 1, x1 = q.z - 1, y1 = q.w - 1;
            bool vx0 = (unsigned)x0 < H_, vy0 = (unsigned)y0 < W_;
            bool vx1 = (unsigned)x1 < H_, vy1 = (unsigned)y1 < W_;
            float v = 0.f;
            if (vx0 && vy0) v += g.x * __ldg(xc + (x0 << 6) + y0);
            if (vx1 && vy1) v += g.y * __ldg(xc + (x1 << 6) + y1);
            if (vx0 && vy1) v += g.z * __ldg(xc + (x0 << 6) + y1);
            if (vx1 && vy0) v += g.w * __ldg(xc + (x1 << 6) + y0);
            xo_s[t * 64 + px] = v;
        }
    }

    // ---- Phase C: GEMM  out[co][px] += Wt[k][co]*xo[k][px] -----------------
    const int pg = tid & 15;   // pixel group: 4 px
    const int cg = tid >> 4;   // channel group: 4 co
    float acc[4][4];
#pragma unroll
    for (int i = 0; i < 4; i++)
#pragma unroll
        for (int j = 0; j < 4; j++) acc[i][j] = 0.f;

    for (int kc = 0; kc < 9; kc++) {
        __syncthreads();
        // load weight chunk Wt[kc*64 .. +64][*] -> w_s[kk][co]
        for (int i = tid; i < 4096; i += 256)
            w_s[i] = g_Wt[kc * 4096 + i];
        __syncthreads();
#pragma unroll 4
        for (int kk = 0; kk < 64; kk++) {
            float4 a  = *(const float4*)&xo_s[(kc * 64 + kk) * 64 + pg * 4];
            float4 wv = *(const float4*)&w_s[kk * 64 + cg * 4];
            acc[0][0] += wv.x * a.x; acc[0][1] += wv.x * a.y; acc[0][2] += wv.x * a.z; acc[0][3] += wv.x * a.w;
            acc[1][0] += wv.y * a.x; acc[1][1] += wv.y * a.y; acc[1][2] += wv.y * a.z; acc[1][3] += wv.y * a.w;
            acc[2][0] += wv.z * a.x; acc[2][1] += wv.z * a.y; acc[2][2] += wv.z * a.z; acc[2][3] += wv.z * a.w;
            acc[3][0] += wv.w * a.x; acc[3][1] += wv.w * a.y; acc[3][2] += wv.w * a.z; acc[3][3] += wv.w * a.w;
        }
    }

    // ---- Epilogue ----------------------------------------------------------
#pragma unroll
    for (int c = 0; c < 4; c++) {
        int co = cg * 4 + c;
        float4 o = make_float4(acc[c][0], acc[c][1], acc[c][2], acc[c][3]);
        *(float4*)&out[(((size_t)b * C_ + co) * H_ + h) * W_ + pg * 4] = o;
    }
}

// ---------------------------------------------------------------------------
extern "C" void kernel_launch(void* const* d_in, const int* in_sizes, int n_in,
                              void* d_out, int out_size) {
    const float* x     = (const float*)d_in[0];
    const float* Woff  = (const float*)d_in[1];
    const float* boff  = (const float*)d_in[2];
    const float* Wconv = (const float*)d_in[3];
    float* out = (float*)d_out;

    cudaFuncSetAttribute(k1_offset_conv,
                         cudaFuncAttributeMaxDynamicSharedMemorySize, K1_SMEM);
    cudaFuncSetAttribute(k2_sample_gemm,
                         cudaFuncAttributeMaxDynamicSharedMemorySize, K2_SMEM);

    k0_transpose_w<<<(C_ * KTOT + 255) / 256, 256>>>(Wconv);
    k1_offset_conv<<<dim3(4, 4, B_), 256, K1_SMEM>>>(x, Woff, boff);
    k2_sample_gemm<<<dim3(H_, B_), 256, K2_SMEM>>>(x, out);
}

// round 2
// speedup vs baseline: 1.4301x; 1.4301x over previous
#include <cuda_runtime.h>
#include <cstdint>

// Problem constants
#define B_  8
#define C_  64
#define H_  64
#define W_  64
#define NN  9          // K*K
#define M_  18         // 2*N offset channels
#define HP  66         // padded H
#define KTOT 576       // C_ * NN
#define CHUNK 72       // k-rows per GEMM chunk (8 ci)
#define NCHUNK 8       // 576 / 72

typedef unsigned long long ull;

// Scratch (device globals: allocation-free rule)
__device__ float g_offset[B_ * M_ * H_ * W_];   // (b, m, h, w)
__device__ float g_Wt[KTOT * C_];               // Wt[k][co] = W_conv[co][k]

// ---------------------------------------------------------------------------
// helpers: packed fp32x2 FMA (Blackwell FFMA2)
// ---------------------------------------------------------------------------
__device__ __forceinline__ void ffma2(ull& d, ull a, ull b) {
    asm("fma.rn.f32x2 %0, %1, %2, %0;" : "+l"(d) : "l"(a), "l"(b));
}
__device__ __forceinline__ float2 unpack2(ull v) {
    float2 r;
    asm("mov.b64 {%0, %1}, %2;" : "=f"(r.x), "=f"(r.y) : "l"(v));
    return r;
}

// ---------------------------------------------------------------------------
// K0: transpose W_conv (co, ci, 3, 3) -> Wt[k][co], k = ci*9 + n
// ---------------------------------------------------------------------------
__global__ void k0_transpose_w(const float* __restrict__ Wc) {
    int i = blockIdx.x * 256 + threadIdx.x;
    if (i < C_ * KTOT) {
        int co = i / KTOT;
        int k  = i % KTOT;
        g_Wt[k * C_ + co] = Wc[i];
    }
}

// ---------------------------------------------------------------------------
// K1: offset conv (3x3, pad 1) -> g_offset
// ---------------------------------------------------------------------------
#define K1_SMEM ((64*18*18 + 18*64*12) * 4)

__global__ __launch_bounds__(256, 1)
void k1_offset_conv(const float* __restrict__ x,
                    const float* __restrict__ Woff,
                    const float* __restrict__ boff) {
    extern __shared__ float smem[];
    float* xs = smem;                 // [ci][18][18]
    float* ws = smem + 64 * 324;      // [m][ci][12]

    const int tid = threadIdx.x;
    const int b   = blockIdx.z;
    const int th0 = blockIdx.y * 16;
    const int tw0 = blockIdx.x * 16;

    const float* xb = x + (size_t)b * C_ * H_ * W_;
    for (int idx = tid; idx < 64 * 324; idx += 256) {
        int ci = idx / 324;
        int rem = idx % 324;
        int r = rem / 18, c = rem % 18;
        int gh = th0 + r - 1, gw = tw0 + c - 1;
        float v = 0.f;
        if ((unsigned)gh < H_ && (unsigned)gw < W_)
            v = xb[(ci * H_ + gh) * W_ + gw];
        xs[idx] = v;
    }
    for (int idx = tid; idx < M_ * 64 * 9; idx += 256) {
        int m  = idx / 576;
        int rem = idx % 576;
        int ci = rem / 9, t = rem % 9;
        ws[(m * 64 + ci) * 12 + t] = Woff[idx];
    }
    __syncthreads();

    const int lh = tid >> 4, lw = tid & 15;
    float acc[M_];
#pragma unroll
    for (int m = 0; m < M_; m++) acc[m] = boff[m];

    for (int ci = 0; ci < 64; ci++) {
        float xv[9];
        const float* xc = xs + ci * 324 + lh * 18 + lw;
#pragma unroll
        for (int u = 0; u < 3; u++)
#pragma unroll
            for (int v = 0; v < 3; v++)
                xv[u * 3 + v] = xc[u * 18 + v];
#pragma unroll
        for (int m = 0; m < M_; m++) {
            const float* wp = ws + (m * 64 + ci) * 12;
            float4 wa = *(const float4*)wp;
            float4 wb = *(const float4*)(wp + 4);
            float  w8 = wp[8];
            acc[m] += xv[0]*wa.x + xv[1]*wa.y + xv[2]*wa.z + xv[3]*wa.w
                    + xv[4]*wb.x + xv[5]*wb.y + xv[6]*wb.z + xv[7]*wb.w
                    + xv[8]*w8;
        }
    }

    const int h = th0 + lh, w = tw0 + lw;
#pragma unroll
    for (int m = 0; m < M_; m++)
        g_offset[((b * M_ + m) * H_ + h) * W_ + w] = acc[m];
}

// ---------------------------------------------------------------------------
// K2: fused bilinear sampling + final GEMM, K-chunked for occupancy 3.
// One block per (b, h) row of 64 output pixels.
// smem: xo chunk [72][64], duplicated weights [72][64] float2, meta [576].
// GEMM inner uses packed fp32x2 FMA (FFMA2): 3 LDS.128 + 8 FFMA2 per kk.
// ---------------------------------------------------------------------------
#define XO_FLOATS (CHUNK * 64)           // 4608
#define W2_FLOATS (CHUNK * 64 * 2)       // 9216
#define SQ_FLOATS (576 * 4)              // int4  x 576
#define SG_FLOATS (576 * 4)              // float4 x 576
#define K2_SMEM ((XO_FLOATS + W2_FLOATS + SQ_FLOATS + SG_FLOATS) * 4)  // 73728 B

__global__ __launch_bounds__(256, 3)
void k2_sample_gemm(const float* __restrict__ x, float* __restrict__ out) {
    extern __shared__ float smem[];
    float*  xo_s = smem;                                   // [72][64]
    float2* w2_s = (float2*)(smem + XO_FLOATS);            // [72][64] duplicated
    int4*   s_q  = (int4*)(smem + XO_FLOATS + W2_FLOATS);  // [576]
    float4* s_g  = (float4*)(smem + XO_FLOATS + W2_FLOATS + SQ_FLOATS); // [576]

    const int tid = threadIdx.x;
    const int h   = blockIdx.x;
    const int b   = blockIdx.y;

    // ---- Phase A: sample positions / bilinear weights ----------------------
    for (int t = tid; t < NN * 64; t += 256) {
        int n  = t / 64;
        int px = t % 64;
        float offx = g_offset[((b * M_ + n)     * H_ + h) * W_ + px];
        float offy = g_offset[((b * M_ + 9 + n) * H_ + h) * W_ + px];
        float pX = (float)(h + 1)  + (float)(n / 3 - 1) + offx;
        float pY = (float)(px + 1) + (float)(n % 3 - 1) + offy;
        float fx = floorf(pX), fy = floorf(pY);
        int x0 = min(max((int)fx,     0), HP - 1);
        int x1 = min(max((int)fx + 1, 0), HP - 1);
        int y0 = min(max((int)fy,     0), HP - 1);
        int y1 = min(max((int)fy + 1, 0), HP - 1);
        float pxc = fminf(fmaxf(pX, 0.f), (float)(HP - 1));
        float pyc = fminf(fmaxf(pY, 0.f), (float)(HP - 1));
        float gx0 = 1.f + (float)x0 - pxc;
        float gx1 = 1.f - ((float)x1 - pxc);
        float gy0 = 1.f + (float)y0 - pyc;
        float gy1 = 1.f - ((float)y1 - pyc);
        s_q[t] = make_int4(x0, y0, x1, y1);
        s_g[t] = make_float4(gx0 * gy0, gx1 * gy1, gx0 * gy1, gx1 * gy0);
    }

    const int pg = tid & 15;   // pixel group: 4 px
    const int cg = tid >> 4;   // channel group: 4 co
    ull acc[4][2];
#pragma unroll
    for (int i = 0; i < 4; i++) { acc[i][0] = 0ull; acc[i][1] = 0ull; }

    const float* xbase = x + (size_t)b * C_ * H_ * W_;

    for (int c = 0; c < NCHUNK; c++) {
        __syncthreads();   // previous GEMM done reading buffers (and meta ready on c=0)

        // load duplicated weight chunk: w2_s[r][co] = {Wt[c*72+r][co], same}
        {
            const float* wsrc = g_Wt + c * (CHUNK * 64);
#pragma unroll
            for (int j = 0; j < CHUNK * 64 / 256; j++) {
                int i = j * 256 + tid;
                float w = wsrc[i];
                w2_s[i] = make_float2(w, w);
            }
        }

        // gather xo chunk rows r=0..71 (k = c*72 + r)
#pragma unroll 3
        for (int j = 0; j < CHUNK * 64 / 256; j++) {   // 18 samples/thread
            int s  = j * 256 + tid;
            int r  = s >> 6;
            int px = s & 63;
            int k  = c * CHUNK + r;
            int ci = k / 9;
            int n  = k % 9;
            int mi = n * 64 + px;
            int4   q = s_q[mi];
            float4 g = s_g[mi];
            const float* xc = xbase + ci * (H_ * W_);
            int x0 = q.x - 1, y0 = q.y - 1, x1 = q.z - 1, y1 = q.w - 1;
            bool vx0 = (unsigned)x0 < H_, vy0 = (unsigned)y0 < W_;
            bool vx1 = (unsigned)x1 < H_, vy1 = (unsigned)y1 < W_;
            float v = 0.f;
            if (vx0 && vy0) v += g.x * __ldg(xc + (x0 << 6) + y0);
            if (vx1 && vy1) v += g.y * __ldg(xc + (x1 << 6) + y1);
            if (vx0 && vy1) v += g.z * __ldg(xc + (x0 << 6) + y1);
            if (vx1 && vy0) v += g.w * __ldg(xc + (x1 << 6) + y0);
            xo_s[r * 64 + px] = v;
        }
        __syncthreads();

        // GEMM chunk: acc[c'][pair] += w2[kk][co] * a[kk][pxpair]
        const ull* wrow = (const ull*)(w2_s + cg * 4);
#pragma unroll 4
        for (int kk = 0; kk < CHUNK; kk++) {
            float4 a = *(const float4*)&xo_s[kk * 64 + pg * 4];
            ull a01 = ((const ull*)&a)[0];
            ull a23 = ((const ull*)&a)[1];
            ull w0 = wrow[kk * 64 + 0];
            ull w1 = wrow[kk * 64 + 1];
            ull w2 = wrow[kk * 64 + 2];
            ull w3 = wrow[kk * 64 + 3];
            ffma2(acc[0][0], w0, a01); ffma2(acc[0][1], w0, a23);
            ffma2(acc[1][0], w1, a01); ffma2(acc[1][1], w1, a23);
            ffma2(acc[2][0], w2, a01); ffma2(acc[2][1], w2, a23);
            ffma2(acc[3][0], w3, a01); ffma2(acc[3][1], w3, a23);
        }
    }

    // ---- Epilogue ----------------------------------------------------------
#pragma unroll
    for (int c = 0; c < 4; c++) {
        int co = cg * 4 + c;
        float2 lo = unpack2(acc[c][0]);
        float2 hi = unpack2(acc[c][1]);
        float4 o = make_float4(lo.x, lo.y, hi.x, hi.y);
        *(float4*)&out[(((size_t)b * C_ + co) * H_ + h) * W_ + pg * 4] = o;
    }
}

// ---------------------------------------------------------------------------
extern "C" void kernel_launch(void* const* d_in, const int* in_sizes, int n_in,
                              void* d_out, int out_size) {
    const float* x     = (const float*)d_in[0];
    const float* Woff  = (const float*)d_in[1];
    const float* boff  = (const float*)d_in[2];
    const float* Wconv = (const float*)d_in[3];
    float* out = (float*)d_out;

    cudaFuncSetAttribute(k1_offset_conv,
                         cudaFuncAttributeMaxDynamicSharedMemorySize, K1_SMEM);
    cudaFuncSetAttribute(k2_sample_gemm,
                         cudaFuncAttributeMaxDynamicSharedMemorySize, K2_SMEM);

    k0_transpose_w<<<(C_ * KTOT + 255) / 256, 256>>>(Wconv);
    k1_offset_conv<<<dim3(4, 4, B_), 256, K1_SMEM>>>(x, Woff, boff);
    k2_sample_gemm<<<dim3(H_, B_), 256, K2_SMEM>>>(x, out);
}

// round 3
// speedup vs baseline: 1.5390x; 1.0762x over previous
#include <cuda_runtime.h>
#include <cstdint>

// Problem constants
#define B_  8
#define C_  64
#define H_  64
#define W_  64
#define NN  9
#define M_  18
#define HP  66
#define KTOT 576
#define CHUNK 36       // k-rows per GEMM chunk (4 ci)
#define NCHUNK 16      // 576 / 36
#define ROWS2 2        // output rows per block
#define PP   128       // pixels per block (2 rows x 64)

typedef unsigned long long ull;

__device__ float g_offset[B_ * M_ * H_ * W_];
__device__ float g_Wt[KTOT * C_];

__device__ __forceinline__ void ffma2(ull& d, ull a, ull b) {
    asm("fma.rn.f32x2 %0, %1, %2, %0;" : "+l"(d) : "l"(a), "l"(b));
}
__device__ __forceinline__ float2 unpack2(ull v) {
    float2 r;
    asm("mov.b64 {%0, %1}, %2;" : "=f"(r.x), "=f"(r.y) : "l"(v));
    return r;
}

// ---------------------------------------------------------------------------
// K0: transpose W_conv (co, ci, 3, 3) -> Wt[k][co]
// ---------------------------------------------------------------------------
__global__ void k0_transpose_w(const float* __restrict__ Wc) {
    int i = blockIdx.x * 256 + threadIdx.x;
    if (i < C_ * KTOT) {
        int co = i / KTOT;
        int k  = i % KTOT;
        g_Wt[k * C_ + co] = Wc[i];
    }
}

// ---------------------------------------------------------------------------
// K1: offset conv (3x3, pad 1) -> g_offset
// ---------------------------------------------------------------------------
#define K1_SMEM ((64*18*18 + 18*64*12) * 4)

__global__ __launch_bounds__(256, 1)
void k1_offset_conv(const float* __restrict__ x,
                    const float* __restrict__ Woff,
                    const float* __restrict__ boff) {
    extern __shared__ float smem[];
    float* xs = smem;                 // [ci][18][18]
    float* ws = smem + 64 * 324;      // [m][ci][12]

    const int tid = threadIdx.x;
    const int b   = blockIdx.z;
    const int th0 = blockIdx.y * 16;
    const int tw0 = blockIdx.x * 16;

    const float* xb = x + (size_t)b * C_ * H_ * W_;
    for (int idx = tid; idx < 64 * 324; idx += 256) {
        int ci = idx / 324;
        int rem = idx % 324;
        int r = rem / 18, c = rem % 18;
        int gh = th0 + r - 1, gw = tw0 + c - 1;
        float v = 0.f;
        if ((unsigned)gh < H_ && (unsigned)gw < W_)
            v = xb[(ci * H_ + gh) * W_ + gw];
        xs[idx] = v;
    }
    for (int idx = tid; idx < M_ * 64 * 9; idx += 256) {
        int m  = idx / 576;
        int rem = idx % 576;
        int ci = rem / 9, t = rem % 9;
        ws[(m * 64 + ci) * 12 + t] = Woff[idx];
    }
    __syncthreads();

    const int lh = tid >> 4, lw = tid & 15;
    float acc[M_];
#pragma unroll
    for (int m = 0; m < M_; m++) acc[m] = boff[m];

    for (int ci = 0; ci < 64; ci++) {
        float xv[9];
        const float* xc = xs + ci * 324 + lh * 18 + lw;
#pragma unroll
        for (int u = 0; u < 3; u++)
#pragma unroll
            for (int v = 0; v < 3; v++)
                xv[u * 3 + v] = xc[u * 18 + v];
#pragma unroll
        for (int m = 0; m < M_; m++) {
            const float* wp = ws + (m * 64 + ci) * 12;
            float4 wa = *(const float4*)wp;
            float4 wb = *(const float4*)(wp + 4);
            float  w8 = wp[8];
            acc[m] += xv[0]*wa.x + xv[1]*wa.y + xv[2]*wa.z + xv[3]*wa.w
                    + xv[4]*wb.x + xv[5]*wb.y + xv[6]*wb.z + xv[7]*wb.w
                    + xv[8]*w8;
        }
    }

    const int h = th0 + lh, w = tw0 + lw;
#pragma unroll
    for (int m = 0; m < M_; m++)
        g_offset[((b * M_ + m) * H_ + h) * W_ + w] = acc[m];
}

// ---------------------------------------------------------------------------
// K2: fused bilinear sampling + final GEMM.
// Block = (b, 2 output rows). 256 threads, 4px x 8co register tile, FFMA2.
// Branchless gather: clamped indices + SEL'd weights (no BSSY/BSYNC).
// ---------------------------------------------------------------------------
#define XO_FLOATS (CHUNK * PP)           // 4608
#define W2_FLOATS (CHUNK * 64 * 2)       // 4608 (float2 units -> floats: 4608*2? see layout)
#define NSAMP     (NN * PP)              // 1152 meta entries

// smem bytes: xo 18432 + w2 18432 + s_c 9216 + s_p 9216 = 55296
#define K2_SMEM (CHUNK*PP*4 + CHUNK*64*8 + NSAMP*8 + NSAMP*8)

__global__ __launch_bounds__(256, 3)
void k2_sample_gemm(const float* __restrict__ x, float* __restrict__ out) {
    extern __shared__ float smem[];
    float*  xo_s = smem;                                       // [36][128]
    float2* w2_s = (float2*)(smem + CHUNK * PP);               // [36][64] dup
    short4* s_c  = (short4*)((char*)smem + CHUNK*PP*4 + CHUNK*64*8);       // [1152]
    float2* s_p  = (float2*)((char*)s_c + NSAMP * 8);                      // [1152]

    const int tid = threadIdx.x;
    const int h0  = blockIdx.x * ROWS2;
    const int b   = blockIdx.y;

    // ---- Phase A: meta (corners + clamped p) -------------------------------
    for (int t = tid; t < NSAMP; t += 256) {
        int n  = t >> 7;           // 0..8
        int pp = t & 127;
        int h  = h0 + (pp >> 6);
        int px = pp & 63;
        float offx = g_offset[((b * M_ + n)     * H_ + h) * W_ + px];
        float offy = g_offset[((b * M_ + 9 + n) * H_ + h) * W_ + px];
        float pX = (float)(h + 1)  + (float)(n / 3 - 1) + offx;
        float pY = (float)(px + 1) + (float)(n % 3 - 1) + offy;
        float fx = floorf(pX), fy = floorf(pY);
        int x0 = min(max((int)fx,     0), HP - 1);
        int x1 = min(max((int)fx + 1, 0), HP - 1);
        int y0 = min(max((int)fy,     0), HP - 1);
        int y1 = min(max((int)fy + 1, 0), HP - 1);
        float pxc = fminf(fmaxf(pX, 0.f), (float)(HP - 1));
        float pyc = fminf(fmaxf(pY, 0.f), (float)(HP - 1));
        s_c[t] = make_short4((short)x0, (short)y0, (short)x1, (short)y1);
        s_p[t] = make_float2(pxc, pyc);
    }

    const int pg = tid & 31;    // px group (4 px), pp = pg*4..pg*4+3
    const int cg = tid >> 5;    // co group (8 co)
    ull acc[8][2];
#pragma unroll
    for (int i = 0; i < 8; i++) { acc[i][0] = 0ull; acc[i][1] = 0ull; }

    const float* xbase = x + (size_t)b * C_ * H_ * W_;

    for (int c = 0; c < NCHUNK; c++) {
        __syncthreads();   // prev GEMM done reading (also covers Phase A on c=0)

        // fill duplicated weight chunk
        {
            const float* wsrc = g_Wt + c * (CHUNK * 64);
#pragma unroll
            for (int j = 0; j < CHUNK * 64 / 256; j++) {
                int i = j * 256 + tid;
                float w = wsrc[i];
                w2_s[i] = make_float2(w, w);
            }
        }

        // branchless gather: 18 samples per thread
#pragma unroll 2
        for (int j = 0; j < CHUNK * PP / 256; j++) {
            int s  = j * 256 + tid;
            int r  = s >> 7;           // k-row in chunk
            int pp = s & 127;
            int k  = c * CHUNK + r;
            int ci = k / 9;
            int n  = k % 9;
            int sid = n * 128 + pp;
            short4 q = s_c[sid];
            float2 p = s_p[sid];
            float gx0 = 1.f + ((float)q.x - p.x);
            float gx1 = 1.f - ((float)q.z - p.x);
            float gy0 = 1.f + ((float)q.y - p.y);
            float gy1 = 1.f - ((float)q.w - p.y);
            int ix0 = q.x - 1, iy0 = q.y - 1, ix1 = q.z - 1, iy1 = q.w - 1;
            // validity in unpadded image
            bool vx0 = (unsigned)ix0 < H_, vy0 = (unsigned)iy0 < W_;
            bool vx1 = (unsigned)ix1 < H_, vy1 = (unsigned)iy1 < W_;
            // clamped (always-legal) addresses
            int cx0 = min(max(ix0, 0), H_ - 1);
            int cx1 = min(max(ix1, 0), H_ - 1);
            int cy0 = min(max(iy0, 0), W_ - 1);
            int cy1 = min(max(iy1, 0), W_ - 1);
            const float* xc = xbase + ci * (H_ * W_);
            float v00 = __ldg(xc + (cx0 << 6) + cy0);
            float v11 = __ldg(xc + (cx1 << 6) + cy1);
            float v01 = __ldg(xc + (cx0 << 6) + cy1);
            float v10 = __ldg(xc + (cx1 << 6) + cy0);
            float w00 = (vx0 && vy0) ? gx0 * gy0 : 0.f;
            float w11 = (vx1 && vy1) ? gx1 * gy1 : 0.f;
            float w01 = (vx0 && vy1) ? gx0 * gy1 : 0.f;
            float w10 = (vx1 && vy0) ? gx1 * gy0 : 0.f;
            xo_s[r * PP + pp] = w00 * v00 + w11 * v11 + w01 * v01 + w10 * v10;
        }
        __syncthreads();

        // GEMM chunk: 16 FFMA2 per kk
#pragma unroll 4
        for (int kk = 0; kk < CHUNK; kk++) {
            float4 a = *(const float4*)&xo_s[kk * PP + pg * 4];
            ull a01 = ((const ull*)&a)[0];
            ull a23 = ((const ull*)&a)[1];
            const ulonglong2* wr = (const ulonglong2*)(w2_s + kk * 64 + cg * 8);
            ulonglong2 wA = wr[0];
            ulonglong2 wB = wr[1];
            ulonglong2 wC = wr[2];
            ulonglong2 wD = wr[3];
            ffma2(acc[0][0], wA.x, a01); ffma2(acc[0][1], wA.x, a23);
            ffma2(acc[1][0], wA.y, a01); ffma2(acc[1][1], wA.y, a23);
            ffma2(acc[2][0], wB.x, a01); ffma2(acc[2][1], wB.x, a23);
            ffma2(acc[3][0], wB.y, a01); ffma2(acc[3][1], wB.y, a23);
            ffma2(acc[4][0], wC.x, a01); ffma2(acc[4][1], wC.x, a23);
            ffma2(acc[5][0], wC.y, a01); ffma2(acc[5][1], wC.y, a23);
            ffma2(acc[6][0], wD.x, a01); ffma2(acc[6][1], wD.x, a23);
            ffma2(acc[7][0], wD.y, a01); ffma2(acc[7][1], wD.y, a23);
        }
    }

    // ---- Epilogue ----------------------------------------------------------
    const int row = pg >> 4;               // 0 or 1
    const int px4 = (pg & 15) * 4;
    const int h   = h0 + row;
#pragma unroll
    for (int cc = 0; cc < 8; cc++) {
        int co = cg * 8 + cc;
        float2 lo = unpack2(acc[cc][0]);
        float2 hi = unpack2(acc[cc][1]);
        float4 o = make_float4(lo.x, lo.y, hi.x, hi.y);
        *(float4*)&out[(((size_t)b * C_ + co) * H_ + h) * W_ + px4] = o;
    }
}

// ---------------------------------------------------------------------------
extern "C" void kernel_launch(void* const* d_in, const int* in_sizes, int n_in,
                              void* d_out, int out_size) {
    const float* x     = (const float*)d_in[0];
    const float* Woff  = (const float*)d_in[1];
    const float* boff  = (const float*)d_in[2];
    const float* Wconv = (const float*)d_in[3];
    float* out = (float*)d_out;

    cudaFuncSetAttribute(k1_offset_conv,
                         cudaFuncAttributeMaxDynamicSharedMemorySize, K1_SMEM);
    cudaFuncSetAttribute(k2_sample_gemm,
                         cudaFuncAttributeMaxDynamicSharedMemorySize, K2_SMEM);

    k0_transpose_w<<<(C_ * KTOT + 255) / 256, 256>>>(Wconv);
    k1_offset_conv<<<dim3(4, 4, B_), 256, K1_SMEM>>>(x, Woff, boff);
    k2_sample_gemm<<<dim3(H_ / ROWS2, B_), 256, K2_SMEM>>>(x, out);
}

// round 4
// speedup vs baseline: 1.7220x; 1.1189x over previous
#include <cuda_runtime.h>
#include <cstdint>

#define B_  8
#define C_  64
#define H_  64
#define W_  64
#define NN  9
#define M_  18
#define HP  66
#define KTOT 576
#define CHUNK 36
#define NCHUNK 16
#define ROWS2 2
#define PP   128

typedef unsigned long long ull;

__device__ float g_offset[B_ * M_ * H_ * W_];
__device__ float g_Wt[KTOT * C_];

__device__ __forceinline__ void ffma2(ull& d, ull a, ull b) {
    asm("fma.rn.f32x2 %0, %1, %2, %0;" : "+l"(d) : "l"(a), "l"(b));
}
__device__ __forceinline__ float2 unpack2(ull v) {
    float2 r;
    asm("mov.b64 {%0, %1}, %2;" : "=f"(r.x), "=f"(r.y) : "l"(v));
    return r;
}
__device__ __forceinline__ ull dup2(float v) {
    ull r;
    asm("mov.b64 %0, {%1, %1};" : "=l"(r) : "f"(v));
    return r;
}
__device__ __forceinline__ ull pack2(float lo, float hi) {
    ull r;
    asm("mov.b64 %0, {%1, %2};" : "=l"(r) : "f"(lo), "f"(hi));
    return r;
}

// ---------------------------------------------------------------------------
// K1: offset conv (3x3, pad 1) -> g_offset.  FFMA2 over m-pairs.
// blockIdx.z == 8 slice performs the W_conv transpose (k0 folded in).
// ---------------------------------------------------------------------------
#define K1_SMEM ((64*324 + 64*9*10*2) * 4)   // xs 82944B + ws2 46080B = 129024B

__global__ __launch_bounds__(256, 1)
void k1_offset_conv(const float* __restrict__ x,
                    const float* __restrict__ Woff,
                    const float* __restrict__ boff,
                    const float* __restrict__ Wc) {
    // ---- folded k0: transpose W_conv ----
    if (blockIdx.z == 8) {
        int base = (blockIdx.y * 4 + blockIdx.x) * 256 + threadIdx.x;
        for (int i = base; i < C_ * KTOT; i += 16 * 256) {
            int co = i / KTOT;
            int k  = i % KTOT;
            g_Wt[k * C_ + co] = Wc[i];
        }
        return;
    }

    extern __shared__ float smem[];
    float*  xs  = smem;                        // [ci][18][18]
    float2* ws2 = (float2*)(smem + 64 * 324);  // [ci][9 pair][10 t]

    const int tid = threadIdx.x;
    const int b   = blockIdx.z;
    const int th0 = blockIdx.y * 16;
    const int tw0 = blockIdx.x * 16;

    const float* xb = x + (size_t)b * C_ * H_ * W_;
    for (int idx = tid; idx < 64 * 324; idx += 256) {
        int ci = idx / 324;
        int rem = idx % 324;
        int r = rem / 18, c = rem % 18;
        int gh = th0 + r - 1, gw = tw0 + c - 1;
        float v = 0.f;
        if ((unsigned)gh < H_ && (unsigned)gw < W_)
            v = xb[(ci * H_ + gh) * W_ + gw];
        xs[idx] = v;
    }
    for (int idx = tid; idx < 64 * 9 * 9; idx += 256) {
        int ci = idx / 81;
        int rem = idx % 81;
        int j = rem / 9, t = rem % 9;
        ws2[(ci * 9 + j) * 10 + t] =
            make_float2(Woff[(2 * j)     * 576 + ci * 9 + t],
                        Woff[(2 * j + 1) * 576 + ci * 9 + t]);
    }
    __syncthreads();

    const int lh = tid >> 4, lw = tid & 15;
    ull acc[9];
#pragma unroll
    for (int j = 0; j < 9; j++) acc[j] = pack2(boff[2 * j], boff[2 * j + 1]);

    for (int ci = 0; ci < 64; ci++) {
        ull xd[9];
        const float* xc = xs + ci * 324 + lh * 18 + lw;
#pragma unroll
        for (int u = 0; u < 3; u++)
#pragma unroll
            for (int v = 0; v < 3; v++)
                xd[u * 3 + v] = dup2(xc[u * 18 + v]);
#pragma unroll
        for (int j = 0; j < 9; j++) {
            const ulonglong2* wp = (const ulonglong2*)(ws2 + (ci * 9 + j) * 10);
            ulonglong2 wA = wp[0];
            ulonglong2 wB = wp[1];
            ulonglong2 wC = wp[2];
            ulonglong2 wD = wp[3];
            ull        wE = *(const ull*)(ws2 + (ci * 9 + j) * 10 + 8);
            ffma2(acc[j], wA.x, xd[0]); ffma2(acc[j], wA.y, xd[1]);
            ffma2(acc[j], wB.x, xd[2]); ffma2(acc[j], wB.y, xd[3]);
            ffma2(acc[j], wC.x, xd[4]); ffma2(acc[j], wC.y, xd[5]);
            ffma2(acc[j], wD.x, xd[6]); ffma2(acc[j], wD.y, xd[7]);
            ffma2(acc[j], wE,   xd[8]);
        }
    }

    const int h = th0 + lh, w = tw0 + lw;
#pragma unroll
    for (int j = 0; j < 9; j++) {
        float2 v = unpack2(acc[j]);
        g_offset[((b * M_ + 2 * j)     * H_ + h) * W_ + w] = v.x;
        g_offset[((b * M_ + 2 * j + 1) * H_ + h) * W_ + w] = v.y;
    }
}

// ---------------------------------------------------------------------------
// K2: fused bilinear sampling + final GEMM.
// Phase A precomputes 4 clamped element addresses + 4 pre-zeroed weights per
// sample; gather is pure LDS.128 + 4 LDG + 4 FFMA. GEMM: 4px x 8co FFMA2.
// ---------------------------------------------------------------------------
#define NSAMP (NN * PP)          // 1152
// smem: xo 18432 + w2dup 18432 + s_q 18432 + s_g 18432 = 73728 B
#define K2_SMEM (CHUNK*PP*4 + CHUNK*64*8 + NSAMP*16 + NSAMP*16)

__global__ __launch_bounds__(256, 3)
void k2_sample_gemm(const float* __restrict__ x, float* __restrict__ out) {
    extern __shared__ float smem[];
    float*  xo_s = smem;                                   // [36][128]
    float2* w2_s = (float2*)(smem + CHUNK * PP);           // [36][64] dup
    int4*   s_q  = (int4*)((char*)smem + CHUNK*PP*4 + CHUNK*64*8);  // [1152]
    float4* s_g  = (float4*)((char*)s_q + NSAMP * 16);              // [1152]

    const int tid = threadIdx.x;
    const int h0  = blockIdx.x * ROWS2;
    const int b   = blockIdx.y;

    // ---- Phase A: addresses + pre-zeroed bilinear weights ------------------
    for (int t = tid; t < NSAMP; t += 256) {
        int n  = t >> 7;
        int pp = t & 127;
        int h  = h0 + (pp >> 6);
        int px = pp & 63;
        float offx = g_offset[((b * M_ + n)     * H_ + h) * W_ + px];
        float offy = g_offset[((b * M_ + 9 + n) * H_ + h) * W_ + px];
        float pX = (float)(h + 1)  + (float)(n / 3 - 1) + offx;
        float pY = (float)(px + 1) + (float)(n % 3 - 1) + offy;
        float fx = floorf(pX), fy = floorf(pY);
        int x0 = min(max((int)fx,     0), HP - 1);
        int x1 = min(max((int)fx + 1, 0), HP - 1);
        int y0 = min(max((int)fy,     0), HP - 1);
        int y1 = min(max((int)fy + 1, 0), HP - 1);
        float pxc = fminf(fmaxf(pX, 0.f), (float)(HP - 1));
        float pyc = fminf(fmaxf(pY, 0.f), (float)(HP - 1));
        float gx0 = 1.f + ((float)x0 - pxc);
        float gx1 = 1.f - ((float)x1 - pxc);
        float gy0 = 1.f + ((float)y0 - pyc);
        float gy1 = 1.f - ((float)y1 - pyc);
        int ix0 = x0 - 1, iy0 = y0 - 1, ix1 = x1 - 1, iy1 = y1 - 1;
        bool vx0 = (unsigned)ix0 < H_, vy0 = (unsigned)iy0 < W_;
        bool vx1 = (unsigned)ix1 < H_, vy1 = (unsigned)iy1 < W_;
        int cx0 = min(max(ix0, 0), H_ - 1);
        int cx1 = min(max(ix1, 0), H_ - 1);
        int cy0 = min(max(iy0, 0), W_ - 1);
        int cy1 = min(max(iy1, 0), W_ - 1);
        s_q[t] = make_int4((cx0 << 6) + cy0, (cx1 << 6) + cy1,
                           (cx0 << 6) + cy1, (cx1 << 6) + cy0);
        s_g[t] = make_float4(vx0 && vy0 ? gx0 * gy0 : 0.f,
                             vx1 && vy1 ? gx1 * gy1 : 0.f,
                             vx0 && vy1 ? gx0 * gy1 : 0.f,
                             vx1 && vy0 ? gx1 * gy0 : 0.f);
    }

    const int pg = tid & 31;
    const int cg = tid >> 5;
    ull acc[8][2];
#pragma unroll
    for (int i = 0; i < 8; i++) { acc[i][0] = 0ull; acc[i][1] = 0ull; }

    const float* xbase = x + (size_t)b * C_ * H_ * W_;

    for (int c = 0; c < NCHUNK; c++) {
        __syncthreads();

        // duplicated weight chunk
        {
            const float* wsrc = g_Wt + c * (CHUNK * 64);
#pragma unroll
            for (int j = 0; j < CHUNK * 64 / 256; j++) {
                int i = j * 256 + tid;
                float w = wsrc[i];
                w2_s[i] = make_float2(w, w);
            }
        }

        // gather: 18 samples/thread, fully precomputed meta
#pragma unroll 3
        for (int j = 0; j < CHUNK * PP / 256; j++) {
            int s  = j * 256 + tid;
            int r  = s >> 7;
            int pp = s & 127;
            int k  = c * CHUNK + r;
            int ci = k / 9;
            int n  = k % 9;
            int sid = n * 128 + pp;
            int4   q = s_q[sid];
            float4 g = s_g[sid];
            const float* xc = xbase + (ci << 12);
            xo_s[r * PP + pp] = g.x * __ldg(xc + q.x) + g.y * __ldg(xc + q.y)
                              + g.z * __ldg(xc + q.z) + g.w * __ldg(xc + q.w);
        }
        __syncthreads();

        // GEMM chunk
#pragma unroll 4
        for (int kk = 0; kk < CHUNK; kk++) {
            float4 a = *(const float4*)&xo_s[kk * PP + pg * 4];
            ull a01 = ((const ull*)&a)[0];
            ull a23 = ((const ull*)&a)[1];
            const ulonglong2* wr = (const ulonglong2*)(w2_s + kk * 64 + cg * 8);
            ulonglong2 wA = wr[0];
            ulonglong2 wB = wr[1];
            ulonglong2 wC = wr[2];
            ulonglong2 wD = wr[3];
            ffma2(acc[0][0], wA.x, a01); ffma2(acc[0][1], wA.x, a23);
            ffma2(acc[1][0], wA.y, a01); ffma2(acc[1][1], wA.y, a23);
            ffma2(acc[2][0], wB.x, a01); ffma2(acc[2][1], wB.x, a23);
            ffma2(acc[3][0], wB.y, a01); ffma2(acc[3][1], wB.y, a23);
            ffma2(acc[4][0], wC.x, a01); ffma2(acc[4][1], wC.x, a23);
            ffma2(acc[5][0], wC.y, a01); ffma2(acc[5][1], wC.y, a23);
            ffma2(acc[6][0], wD.x, a01); ffma2(acc[6][1], wD.x, a23);
            ffma2(acc[7][0], wD.y, a01); ffma2(acc[7][1], wD.y, a23);
        }
    }

    // ---- Epilogue ----------------------------------------------------------
    const int row = pg >> 4;
    const int px4 = (pg & 15) * 4;
    const int h   = h0 + row;
#pragma unroll
    for (int cc = 0; cc < 8; cc++) {
        int co = cg * 8 + cc;
        float2 lo = unpack2(acc[cc][0]);
        float2 hi = unpack2(acc[cc][1]);
        float4 o = make_float4(lo.x, lo.y, hi.x, hi.y);
        *(float4*)&out[(((size_t)b * C_ + co) * H_ + h) * W_ + px4] = o;
    }
}

// ---------------------------------------------------------------------------
extern "C" void kernel_launch(void* const* d_in, const int* in_sizes, int n_in,
                              void* d_out, int out_size) {
    const float* x     = (const float*)d_in[0];
    const float* Woff  = (const float*)d_in[1];
    const float* boff  = (const float*)d_in[2];
    const float* Wconv = (const float*)d_in[3];
    float* out = (float*)d_out;

    cudaFuncSetAttribute(k1_offset_conv,
                         cudaFuncAttributeMaxDynamicSharedMemorySize, K1_SMEM);
    cudaFuncSetAttribute(k2_sample_gemm,
                         cudaFuncAttributeMaxDynamicSharedMemorySize, K2_SMEM);

    k1_offset_conv<<<dim3(4, 4, 9), 256, K1_SMEM>>>(x, Woff, boff, Wconv);
    k2_sample_gemm<<<dim3(H_ / ROWS2, B_), 256, K2_SMEM>>>(x, out);
}

// round 6
// speedup vs baseline: 1.9136x; 1.1112x over previous
#include <cuda_runtime.h>
#include <cstdint>

#define B_  8
#define C_  64
#define H_  64
#define W_  64
#define NN  9
#define M_  18
#define HP  66
#define KTOT 576

typedef unsigned long long ull;

__device__ float g_offset[B_ * M_ * H_ * W_];
__device__ float g_Wp[KTOT * C_];   // permuted: g_Wp[(n*64+ci)*64 + co] = Wc[co][ci*9+n]

// ---------------- helpers ----------------
__device__ __forceinline__ void ffma2(ull& d, ull a, ull b) {
    asm("fma.rn.f32x2 %0, %1, %2, %0;" : "+l"(d) : "l"(a), "l"(b));
}
__device__ __forceinline__ float2 unpack2(ull v) {
    float2 r; asm("mov.b64 {%0, %1}, %2;" : "=f"(r.x), "=f"(r.y) : "l"(v)); return r;
}
__device__ __forceinline__ ull dup2(float v) {
    ull r; asm("mov.b64 %0, {%1, %1};" : "=l"(r) : "f"(v)); return r;
}
__device__ __forceinline__ ull pack2(float lo, float hi) {
    ull r; asm("mov.b64 %0, {%1, %2};" : "=l"(r) : "f"(lo), "f"(hi)); return r;
}

// ---------------------------------------------------------------------------
// K1: offset conv (FFMA2 over m-pairs).  z==8 slice preps permuted g_Wp.
// ---------------------------------------------------------------------------
#define K1_SMEM ((64*324 + 64*9*10*2) * 4)   // 129024 B

__global__ __launch_bounds__(256, 1)
void k1_offset_conv(const float* __restrict__ x,
                    const float* __restrict__ Woff,
                    const float* __restrict__ boff,
                    const float* __restrict__ Wc) {
    if (blockIdx.z == 8) {
        int base = (blockIdx.y * 4 + blockIdx.x) * 256 + threadIdx.x;
        for (int i = base; i < KTOT * C_; i += 16 * 256) {
            int kp = i >> 6;            // permuted k
            int co = i & 63;
            int n  = kp >> 6;
            int ci = kp & 63;
            g_Wp[i] = Wc[co * KTOT + ci * 9 + n];
        }
        return;
    }

    extern __shared__ float smem[];
    float*  xs  = smem;                        // [ci][18][18]
    float2* ws2 = (float2*)(smem + 64 * 324);  // [ci][9][10]

    const int tid = threadIdx.x;
    const int b   = blockIdx.z;
    const int th0 = blockIdx.y * 16;
    const int tw0 = blockIdx.x * 16;

    const float* xb = x + (size_t)b * C_ * H_ * W_;
    for (int idx = tid; idx < 64 * 324; idx += 256) {
        int ci = idx / 324;
        int rem = idx % 324;
        int r = rem / 18, c = rem % 18;
        int gh = th0 + r - 1, gw = tw0 + c - 1;
        float v = 0.f;
        if ((unsigned)gh < H_ && (unsigned)gw < W_)
            v = xb[(ci * H_ + gh) * W_ + gw];
        xs[idx] = v;
    }
    for (int idx = tid; idx < 64 * 81; idx += 256) {
        int ci = idx / 81;
        int rem = idx % 81;
        int j = rem / 9, t = rem % 9;
        ws2[(ci * 9 + j) * 10 + t] =
            make_float2(Woff[(2 * j)     * 576 + ci * 9 + t],
                        Woff[(2 * j + 1) * 576 + ci * 9 + t]);
    }
    __syncthreads();

    const int lh = tid >> 4, lw = tid & 15;
    ull acc[9];
#pragma unroll
    for (int j = 0; j < 9; j++) acc[j] = pack2(boff[2 * j], boff[2 * j + 1]);

    for (int ci = 0; ci < 64; ci++) {
        ull xd[9];
        const float* xc = xs + ci * 324 + lh * 18 + lw;
#pragma unroll
        for (int u = 0; u < 3; u++)
#pragma unroll
            for (int v = 0; v < 3; v++)
                xd[u * 3 + v] = dup2(xc[u * 18 + v]);
#pragma unroll
        for (int j = 0; j < 9; j++) {
            const ulonglong2* wp = (const ulonglong2*)(ws2 + (ci * 9 + j) * 10);
            ulonglong2 wA = wp[0];
            ulonglong2 wB = wp[1];
            ulonglong2 wC = wp[2];
            ulonglong2 wD = wp[3];
            ull        wE = *(const ull*)(ws2 + (ci * 9 + j) * 10 + 8);
            ffma2(acc[j], wA.x, xd[0]); ffma2(acc[j], wA.y, xd[1]);
            ffma2(acc[j], wB.x, xd[2]); ffma2(acc[j], wB.y, xd[3]);
            ffma2(acc[j], wC.x, xd[4]); ffma2(acc[j], wC.y, xd[5]);
            ffma2(acc[j], wD.x, xd[6]); ffma2(acc[j], wD.y, xd[7]);
            ffma2(acc[j], wE,   xd[8]);
        }
    }

    const int h = th0 + lh, w = tw0 + lw;
#pragma unroll
    for (int j = 0; j < 9; j++) {
        float2 v = unpack2(acc[j]);
        g_offset[((b * M_ + 2 * j)     * H_ + h) * W_ + w] = v.x;
        g_offset[((b * M_ + 2 * j + 1) * H_ + h) * W_ + w] = v.y;
    }
}

// ---------------------------------------------------------------------------
// K2: fused bilinear sampling + GEMM.  Block = (b, 1 row) = 64 px, 256 thr.
// K permuted as k' = n*64+ci: chunk = one n x 64 ci -> meta loaded once/chunk.
// GEMM: 4px x 4co per thread, FFMA2, weights dup'd in regs (ALU pipe).
// smem: meta 13.8KB + xo 16KB + B 16KB = 46.6KB -> occupancy 4.
// ---------------------------------------------------------------------------
#define NSAMP 576               // 9 * 64
#define SM_Q  0                                  // ushort4[576] = 4608
#define SM_G  (SM_Q + NSAMP * 8)                 // float4[576]  = 9216
#define SM_XO (SM_G + NSAMP * 16)                // [64 ci][64 px] = 16384
#define SM_W  (SM_XO + 64 * 64 * 4)              // [64 k][64 co]  = 16384
#define K2_SMEM (SM_W + 64 * 64 * 4)             // 46592

__global__ __launch_bounds__(256, 4)
void k2_sample_gemm(const float* __restrict__ x, float* __restrict__ out) {
    extern __shared__ char smc[];
    ushort4* s_q  = (ushort4*)(smc + SM_Q);
    float4*  s_g  = (float4*)(smc + SM_G);
    float*   xo_s = (float*)(smc + SM_XO);
    float*   w_s  = (float*)(smc + SM_W);

    const int tid = threadIdx.x;
    const int h   = blockIdx.x;
    const int b   = blockIdx.y;

    // ---- Phase A: 4 clamped element-offsets + pre-zeroed weights -----------
    for (int t = tid; t < NSAMP; t += 256) {
        int n  = t >> 6;
        int px = t & 63;
        float offx = g_offset[((b * M_ + n)     * H_ + h) * W_ + px];
        float offy = g_offset[((b * M_ + 9 + n) * H_ + h) * W_ + px];
        float pX = (float)(h + 1)  + (float)(n / 3 - 1) + offx;
        float pY = (float)(px + 1) + (float)(n % 3 - 1) + offy;
        float fx = floorf(pX), fy = floorf(pY);
        int x0 = min(max((int)fx,     0), HP - 1);
        int x1 = min(max((int)fx + 1, 0), HP - 1);
        int y0 = min(max((int)fy,     0), HP - 1);
        int y1 = min(max((int)fy + 1, 0), HP - 1);
        float pxc = fminf(fmaxf(pX, 0.f), (float)(HP - 1));
        float pyc = fminf(fmaxf(pY, 0.f), (float)(HP - 1));
        float gx0 = 1.f + ((float)x0 - pxc);
        float gx1 = 1.f - ((float)x1 - pxc);
        float gy0 = 1.f + ((float)y0 - pyc);
        float gy1 = 1.f - ((float)y1 - pyc);
        int ix0 = x0 - 1, iy0 = y0 - 1, ix1 = x1 - 1, iy1 = y1 - 1;
        bool vx0 = (unsigned)ix0 < H_, vy0 = (unsigned)iy0 < W_;
        bool vx1 = (unsigned)ix1 < H_, vy1 = (unsigned)iy1 < W_;
        int cx0 = min(max(ix0, 0), H_ - 1);
        int cx1 = min(max(ix1, 0), H_ - 1);
        int cy0 = min(max(iy0, 0), W_ - 1);
        int cy1 = min(max(iy1, 0), W_ - 1);
        s_q[t] = make_ushort4((unsigned short)((cx0 << 6) + cy0),
                              (unsigned short)((cx1 << 6) + cy1),
                              (unsigned short)((cx0 << 6) + cy1),
                              (unsigned short)((cx1 << 6) + cy0));
        s_g[t] = make_float4(vx0 && vy0 ? gx0 * gy0 : 0.f,
                             vx1 && vy1 ? gx1 * gy1 : 0.f,
                             vx0 && vy1 ? gx0 * gy1 : 0.f,
                             vx1 && vy0 ? gx1 * gy0 : 0.f);
    }

    const int px = tid & 63;        // gather: fixed pixel
    const int qq = tid >> 6;        // gather: ci quarter
    const int pg = tid >> 4;        // GEMM: 16 groups x 4 px
    const int cg = tid & 15;        // GEMM: 16 groups x 4 co
    const float* xbase = x + (size_t)b * C_ * H_ * W_;

    ull acc[4][2];
#pragma unroll
    for (int i = 0; i < 4; i++) { acc[i][0] = 0ull; acc[i][1] = 0ull; }

    for (int n = 0; n < NN; n++) {
        __syncthreads();   // previous GEMM finished reading xo_s/w_s (covers Phase A at n=0)

        // B chunk: w_s[k][co], k = ci (within chunk n)
        {
            const float4* src = (const float4*)(g_Wp + n * 4096);
            float4* dst = (float4*)w_s;
#pragma unroll
            for (int j = 0; j < 4; j++)
                dst[j * 256 + tid] = src[j * 256 + tid];
        }

        // gather: meta once, 16 ci per thread
        {
            ushort4 q = s_q[n * 64 + px];
            float4  g = s_g[n * 64 + px];
#pragma unroll 4
            for (int i = 0; i < 16; i++) {
                int ci = qq * 16 + i;
                const float* xc = xbase + (ci << 12);
                float v = g.x * __ldg(xc + q.x) + g.y * __ldg(xc + q.y)
                        + g.z * __ldg(xc + q.z) + g.w * __ldg(xc + q.w);
                xo_s[ci * 64 + px] = v;
            }
        }
        __syncthreads();

        // GEMM chunk: 64 kk, 8 FFMA2/kk
#pragma unroll 8
        for (int kk = 0; kk < 64; kk++) {
            float4 a = *(const float4*)&xo_s[kk * 64 + pg * 4];
            float4 w = *(const float4*)&w_s[kk * 64 + cg * 4];
            ull a01 = ((const ull*)&a)[0];
            ull a23 = ((const ull*)&a)[1];
            ull w0 = dup2(w.x), w1 = dup2(w.y), w2 = dup2(w.z), w3 = dup2(w.w);
            ffma2(acc[0][0], w0, a01); ffma2(acc[0][1], w0, a23);
            ffma2(acc[1][0], w1, a01); ffma2(acc[1][1], w1, a23);
            ffma2(acc[2][0], w2, a01); ffma2(acc[2][1], w2, a23);
            ffma2(acc[3][0], w3, a01); ffma2(acc[3][1], w3, a23);
        }
    }

    // ---- Epilogue ----------------------------------------------------------
#pragma unroll
    for (int c = 0; c < 4; c++) {
        int co = cg * 4 + c;
        float2 lo = unpack2(acc[c][0]);
        float2 hi = unpack2(acc[c][1]);
        float4 o = make_float4(lo.x, lo.y, hi.x, hi.y);
        *(float4*)&out[(((size_t)b * C_ + co) * H_ + h) * W_ + pg * 4] = o;
    }
}

// ---------------------------------------------------------------------------
extern "C" void kernel_launch(void* const* d_in, const int* in_sizes, int n_in,
                              void* d_out, int out_size) {
    const float* x     = (const float*)d_in[0];
    const float* Woff  = (const float*)d_in[1];
    const float* boff  = (const float*)d_in[2];
    const float* Wconv = (const float*)d_in[3];
    float* out = (float*)d_out;

    cudaFuncSetAttribute(k1_offset_conv,
                         cudaFuncAttributeMaxDynamicSharedMemorySize, K1_SMEM);
    cudaFuncSetAttribute(k2_sample_gemm,
                         cudaFuncAttributeMaxDynamicSharedMemorySize, K2_SMEM);

    k1_offset_conv<<<dim3(4, 4, 9), 256, K1_SMEM>>>(x, Woff, boff, Wconv);
    k2_sample_gemm<<<dim3(H_, B_), 256, K2_SMEM>>>(x, out);
}